// round 3
// baseline (speedup 1.0000x reference)
#include <cuda_runtime.h>

// Row-wise softmax (no max subtraction): y = exp(x) / sum(exp(x), axis=-1)
// x: (16384, 4096) fp32.
// Persistent-CTA version: 592 CTAs (148 SM x 4), 256 threads, each CTA walks
// rows grid-strided. Row r+stride's loads are issued BEFORE row r's
// reduce/store phase (register double buffer), so the HBM read stream never
// drains during barriers/stores and there are no wave-transition bubbles.

#define COLS 4096
#define THREADS 256
#define VPT 4                 // 4 x float4 = 16 floats/thread; 256*16 = 4096
#define NUM_SMS 148
#define CTAS_PER_SM 4

__global__ __launch_bounds__(THREADS, CTAS_PER_SM)
void softmax_persist_kernel(const float4* __restrict__ x,
                            float4* __restrict__ y, int rows) {
    const int tid = threadIdx.x;
    const int stride = gridDim.x;
    int r = blockIdx.x;

    __shared__ float warp_sums[THREADS / 32];

    // Prologue: load first row into cur.
    float4 cur[VPT];
    {
        const float4* xr = x + (size_t)r * (COLS / 4);
#pragma unroll
        for (int i = 0; i < VPT; ++i)
            cur[i] = xr[tid + i * THREADS];
    }

    while (r < rows) {
        const int rn = r + stride;

        // Prefetch next row (loads issued now, consumed next iteration;
        // they remain in flight across the barriers below).
        float4 nxt[VPT];
        if (rn < rows) {
            const float4* xn = x + (size_t)rn * (COLS / 4);
#pragma unroll
            for (int i = 0; i < VPT; ++i)
                nxt[i] = xn[tid + i * THREADS];
        } else {
#pragma unroll
            for (int i = 0; i < VPT; ++i)
                nxt[i] = make_float4(0.f, 0.f, 0.f, 0.f);
        }

        // exp + local sum on current row (registers only).
        float local = 0.0f;
#pragma unroll
        for (int i = 0; i < VPT; ++i) {
            cur[i].x = __expf(cur[i].x);
            cur[i].y = __expf(cur[i].y);
            cur[i].z = __expf(cur[i].z);
            cur[i].w = __expf(cur[i].w);
            local += (cur[i].x + cur[i].y) + (cur[i].z + cur[i].w);
        }

        // Block reduction.
#pragma unroll
        for (int o = 16; o > 0; o >>= 1)
            local += __shfl_xor_sync(0xFFFFFFFFu, local, o);
        if ((tid & 31) == 0)
            warp_sums[tid >> 5] = local;
        __syncthreads();

        float total = 0.0f;
#pragma unroll
        for (int w = 0; w < THREADS / 32; ++w)
            total += warp_sums[w];
        const float inv = 1.0f / total;

        // Scale + store current row.
        float4* yr = y + (size_t)r * (COLS / 4);
#pragma unroll
        for (int i = 0; i < VPT; ++i) {
            float4 t = cur[i];
            t.x *= inv;
            t.y *= inv;
            t.z *= inv;
            t.w *= inv;
            yr[tid + i * THREADS] = t;
        }

        // Protect warp_sums against next iteration's writes.
        __syncthreads();

#pragma unroll
        for (int i = 0; i < VPT; ++i)
            cur[i] = nxt[i];
        r = rn;
    }
}

extern "C" void kernel_launch(void* const* d_in, const int* in_sizes, int n_in,
                              void* d_out, int out_size) {
    const float4* x = (const float4*)d_in[0];
    float4* y = (float4*)d_out;
    const int rows = in_sizes[0] / COLS;  // 16384
    int grid = NUM_SMS * CTAS_PER_SM;    // 592 persistent CTAs
    if (grid > rows) grid = rows;
    softmax_persist_kernel<<<grid, THREADS>>>(x, y, rows);
}

// round 4
// speedup vs baseline: 1.0974x; 1.0974x over previous
#include <cuda_runtime.h>

// Row-wise softmax (no max subtraction, matching reference):
//   y = exp(x) / sum(exp(x), axis=-1)
// x: (16384, 4096) fp32.
// R1 geometry (best measured: 73.6us, DRAM 82.5%, occ 90.6%):
//   1 CTA per row, 256 threads, 16 elems/thread in registers (4x float4).
// Single change vs R1: stores use .cs (evict-first) so the never-re-read
// output stream doesn't churn L2 against the read stream.

#define COLS 4096
#define THREADS 256
#define VECS_PER_THREAD 4   // 4 float4 = 16 floats; 256*16 = 4096

__device__ __forceinline__ void stcs4(float4* p, float4 v) {
    asm volatile("st.global.cs.v4.f32 [%0], {%1,%2,%3,%4};"
                 :: "l"(p), "f"(v.x), "f"(v.y), "f"(v.z), "f"(v.w));
}

__global__ __launch_bounds__(THREADS, 8)
void softmax_row_kernel(const float4* __restrict__ x, float4* __restrict__ y) {
    const int row = blockIdx.x;
    const size_t base = (size_t)row * (COLS / 4);
    const float4* xr = x + base;
    float4* yr = y + base;
    const int tid = threadIdx.x;

    float4 v[VECS_PER_THREAD];
    float local = 0.0f;

    // Front-batched vector loads (MLP=4), exp on the fly, keep in registers.
#pragma unroll
    for (int i = 0; i < VECS_PER_THREAD; ++i) {
        float4 t = xr[tid + i * THREADS];
        t.x = __expf(t.x);
        t.y = __expf(t.y);
        t.z = __expf(t.z);
        t.w = __expf(t.w);
        local += (t.x + t.y) + (t.z + t.w);
        v[i] = t;
    }

    // Block reduction: warp shuffle then cross-warp via smem broadcast.
    __shared__ float warp_sums[THREADS / 32];
#pragma unroll
    for (int o = 16; o > 0; o >>= 1)
        local += __shfl_xor_sync(0xFFFFFFFFu, local, o);
    if ((tid & 31) == 0)
        warp_sums[tid >> 5] = local;
    __syncthreads();

    float total = 0.0f;
#pragma unroll
    for (int w = 0; w < THREADS / 32; ++w)
        total += warp_sums[w];  // broadcast LDS, conflict-free

    const float inv = 1.0f / total;

#pragma unroll
    for (int i = 0; i < VECS_PER_THREAD; ++i) {
        float4 t = v[i];
        t.x *= inv;
        t.y *= inv;
        t.z *= inv;
        t.w *= inv;
        stcs4(yr + tid + i * THREADS, t);
    }
}

extern "C" void kernel_launch(void* const* d_in, const int* in_sizes, int n_in,
                              void* d_out, int out_size) {
    const float4* x = (const float4*)d_in[0];
    float4* y = (float4*)d_out;
    const int rows = in_sizes[0] / COLS;  // 16384
    softmax_row_kernel<<<rows, THREADS>>>(x, y);
}

// round 6
// speedup vs baseline: 1.1130x; 1.0142x over previous
#include <cuda_runtime.h>

// Row-wise softmax (no max subtraction): y = exp(x) / sum(exp(x), axis=-1)
// x: (16384, 4096) fp32.
// 1 CTA per row, 512 threads, 8 elems/thread (2x float4) in registers.
// vs R1 (256thr/VPT4): same in-flight bytes per SM, but oe*MLP_p1 drops
// 32 -> 8 (< Q_th 16), eliminating the cross-CTA L1tex-queue contention
// slope in the B300 spread model.

#define COLS 4096
#define THREADS 512
#define VPT 2   // 2 x float4 = 8 floats; 512*8 = 4096

__global__ __launch_bounds__(THREADS, 4)
void softmax_row512_kernel(const float4* __restrict__ x,
                           float4* __restrict__ y) {
    const int row = blockIdx.x;
    const size_t base = (size_t)row * (COLS / 4);
    const float4* xr = x + base;
    float4* yr = y + base;
    const int tid = threadIdx.x;

    float4 v[VPT];
    float local = 0.0f;

    // Front-batched vector loads (MLP_p1 = 2), exp on the fly.
#pragma unroll
    for (int i = 0; i < VPT; ++i) {
        float4 t = xr[tid + i * THREADS];
        t.x = __expf(t.x);
        t.y = __expf(t.y);
        t.z = __expf(t.z);
        t.w = __expf(t.w);
        local += (t.x + t.y) + (t.z + t.w);
        v[i] = t;
    }

    // Block reduction: warp shuffle then 16 warp sums via smem broadcast.
    __shared__ float warp_sums[THREADS / 32];
#pragma unroll
    for (int o = 16; o > 0; o >>= 1)
        local += __shfl_xor_sync(0xFFFFFFFFu, local, o);
    if ((tid & 31) == 0)
        warp_sums[tid >> 5] = local;
    __syncthreads();

    float total = 0.0f;
#pragma unroll
    for (int w = 0; w < THREADS / 32; ++w)
        total += warp_sums[w];  // broadcast LDS, conflict-free

    const float inv = 1.0f / total;

#pragma unroll
    for (int i = 0; i < VPT; ++i) {
        float4 t = v[i];
        t.x *= inv;
        t.y *= inv;
        t.z *= inv;
        t.w *= inv;
        yr[tid + i * THREADS] = t;
    }
}

extern "C" void kernel_launch(void* const* d_in, const int* in_sizes, int n_in,
                              void* d_out, int out_size) {
    const float4* x = (const float4*)d_in[0];
    float4* y = (float4*)d_out;
    const int rows = in_sizes[0] / COLS;  // 16384
    softmax_row512_kernel<<<rows, THREADS>>>(x, y);
}